// round 13
// baseline (speedup 1.0000x reference)
#include <cuda_runtime.h>
#include <stdint.h>

// ExtractSearchWindows: out[b,y,x, wy*7+wx, ty*7+tx] = Qpad[b][y+wy+ty][x+wx+tx]
// Qpad = zero-padded (pad=6) image, values = trunc(input) in [0,255). Output f32.
//
// 708 MB f32 stores -> pure store-BW problem. SINGLE launch; block (slice,row)
// of 512 threads (4 blocks/SM = full 64 warp slots): builds a 13-row table
// (pitch 268: 268 mod 32 = 12 makes the stride-4 gather bank-conflict-free;
// column-shifted +2 so interior loads/stores are float4-aligned) + up to 260
// chunk descriptors in smem, then streams the slice's float4 chunks x 12
// x-groups as 32B units of 2 STG.128 (u-major lane map keeps stores coalesced).
// grid(37,384): slice fastest -> each 592-block wave covers 16 FULL consecutive
// rows (~28 MB contiguous output), W = 24.00 waves exactly.

#define T_ROWS    13
#define T_PITCH   268            // mod 32 = 12: kills systematic LDS conflicts
#define NT        512
#define SLICE     260            // chunks per slice; 37*260 = 9620 >= 9604
#define NCHUNKS   9604           // float4 chunks per 38416-elem (16-x) region
#define NUNITS    (SLICE * 6)    // 1560 (u, xg-pair) units per block
#define ROW_ELEMS 460992         // 192 * 2401 floats per (b,y) row
#define XG_STRIDE 9604           // float4 stride between x-groups (38416/4)

__global__ __launch_bounds__(NT) void main_k(const float* __restrict__ in,
                                             float* __restrict__ out) {
    __shared__ float   Tsh[T_ROWS * T_PITCH];
    __shared__ ushort4 Dsh[SLICE];

    int usl   = blockIdx.x;              // 0..36  (fastest-varying)
    int rowid = blockIdx.y;              // 0..383 = b*192 + y
    int b   = rowid / 192;
    int y   = rowid - b * 192;
    int tid = threadIdx.x;
    int ubase = usl * SLICE;

    // ---- Prologue A (vectorized): row table, col-shifted layout ----
    // Tsh[r*268 + t] = Qpad[b][y+r][t-2]; Qpad col = gc+6, so t = gc+8:
    // interior cols gc in [0,192) sit at t in [8,200), 16B-aligned in both
    // gmem and smem (268 % 4 == 0). 13 x 52 float4 units, 1.32/thread.
    const float* inb = in + (size_t)b * 192 * 192;
    for (int idx = tid; idx < T_ROWS * 52; idx += NT) {
        int r   = idx / 52;
        int t4  = idx - r * 52;          // float4 column 0..51 (t = 4*t4)
        int gr  = y + r - 6;             // global image row
        int gc0 = t4 * 4 - 8;            // global image col of lane 0
        float4 v = make_float4(0.f, 0.f, 0.f, 0.f);
        if ((unsigned)gr < 192u && (unsigned)gc0 < 192u) {
            float4 w = *(const float4*)(inb + gr * 192 + gc0);
            v.x = (float)__float2uint_rz(w.x);
            v.y = (float)__float2uint_rz(w.y);
            v.z = (float)__float2uint_rz(w.z);
            v.w = (float)__float2uint_rz(w.w);
        }
        *(float4*)&Tsh[r * T_PITCH + t4 * 4] = v;
    }

    // ---- Prologue B: per-chunk descriptors for this slice ----
    // Chunk u covers elements [4u,4u+4) of the 38416-elem 16-x region.
    // Element e: xi=e/2401, rr=e%2401 -> w=rr/49 (wy,wx), p=rr%49 (ty,tx);
    // smem offset = (wy+ty)*T_PITCH + (xi+wx+tx) + 2 (column shift);
    // runtime adds 16*xg. Chunks past NCHUNKS are clamped (stores guarded).
    if (tid < SLICE) {
        int u = ubase + tid;
        if (u >= NCHUNKS) u = NCHUNKS - 1;
        unsigned short off[4];
#pragma unroll
        for (int j = 0; j < 4; j++) {
            int e  = 4 * u + j;
            int xi = e / 2401;
            int rr = e - xi * 2401;
            int w  = rr / 49;
            int p  = rr - w * 49;
            int wy = w / 7, wx = w - wy * 7;
            int ty = p / 7, tx = p - ty * 7;
            off[j] = (unsigned short)((wy + ty) * T_PITCH + (xi + wx + tx) + 2);
        }
        Dsh[tid] = make_ushort4(off[0], off[1], off[2], off[3]);
    }
    __syncthreads();

    // ---- Main store stream: units of 2 coalesced STG.128 ----
    float4* rowout4 = (float4*)(out + (size_t)rowid * ROW_ELEMS);

#pragma unroll 1
    for (int idx = tid; idx < NUNITS; idx += NT) {
        int xgp = idx / SLICE;           // 0..5 (pair of x-groups)
        int uu  = idx - xgp * SLICE;     // 0..259, u-major: lanes coalesced
        int u   = ubase + uu;
        if (u < NCHUNKS) {               // warp-uniform except at slice edge
            ushort4 d = Dsh[uu];
            float4* gp = rowout4 + u;

            int xg0 = 2 * xgp;
#pragma unroll
            for (int j = 0; j < 2; j++) {
                int st = (xg0 + j) * 16; // +16 table columns per x-group
                float4 v;
                v.x = Tsh[d.x + st];
                v.y = Tsh[d.y + st];
                v.z = Tsh[d.z + st];
                v.w = Tsh[d.w + st];
                __stcs(gp + (size_t)(xg0 + j) * XG_STRIDE, v);
            }
        }
    }
}

// ---------------------------------------------------------------- launcher

extern "C" void kernel_launch(void* const* d_in, const int* in_sizes, int n_in,
                              void* d_out, int out_size) {
    const float* in = (const float*)d_in[0];
    // d_in[1] = search_range (fixed at 3: cv=7, offset=0 baked into descriptors)

    dim3 grid(37, 384);                  // x=slice fastest -> waves = 16 full rows
    main_k<<<grid, NT>>>(in, (float*)d_out);
}

// round 14
// speedup vs baseline: 1.0050x; 1.0050x over previous
#include <cuda_runtime.h>
#include <stdint.h>

// ExtractSearchWindows: out[b,y,x, wy*7+wx, ty*7+tx] = Qpad[b][y+wy+ty][x+wx+tx]
// Qpad = zero-padded (pad=6) image, values = trunc(input) in [0,255). Output f32.
//
// 708 MB f32 stores -> pure store-BW problem. SINGLE launch; block (slice,row)
// of 512 threads (4 blocks/SM = full 64 warp slots): builds a 13x208 row table
// (column-shifted +2 so interior loads/stores are float4-aligned) + up to 260
// chunk descriptors in smem, then streams the slice's float4 chunks x 12
// x-groups as 260x4 units of 3 STG.128 (u-major lane map keeps stores
// coalesced; 1040/512 = 2.03 units/thread -> near-perfect balance).
// grid(37,384): slice fastest -> each 592-block wave covers 16 FULL consecutive
// rows (~28 MB contiguous output), W = 24.00 waves exactly.

#define T_ROWS    13
#define T_COLS    208
#define NT        512
#define SLICE     260            // chunks per slice; 37*260 = 9620 >= 9604
#define NCHUNKS   9604           // float4 chunks per 38416-elem (16-x) region
#define NUNITS    (SLICE * 4)    // 1040 (u, xg-triple) units per block
#define ROW_ELEMS 460992         // 192 * 2401 floats per (b,y) row
#define XG_STRIDE 9604           // float4 stride between x-groups (38416/4)

__global__ __launch_bounds__(NT) void main_k(const float* __restrict__ in,
                                             float* __restrict__ out) {
    __shared__ float   Tsh[T_ROWS * T_COLS];
    __shared__ ushort4 Dsh[SLICE];

    int usl   = blockIdx.x;              // 0..36  (fastest-varying)
    int rowid = blockIdx.y;              // 0..383 = b*192 + y
    int b   = rowid / 192;
    int y   = rowid - b * 192;
    int tid = threadIdx.x;
    int ubase = usl * SLICE;

    // ---- Prologue A (vectorized): row table, col-shifted layout ----
    // Tsh[r*208 + t] = Qpad[b][y+r][t-2]; Qpad col = gc+6, so t = gc+8:
    // interior cols gc in [0,192) sit at t in [8,200), 16B-aligned in both
    // gmem and smem. 13 x 52 float4 units, 1.32/thread, one L2 round.
    const float* inb = in + (size_t)b * 192 * 192;
    for (int idx = tid; idx < T_ROWS * 52; idx += NT) {
        int r   = idx / 52;
        int t4  = idx - r * 52;          // float4 column 0..51
        int gr  = y + r - 6;             // global image row
        int gc0 = t4 * 4 - 8;            // global image col of lane 0
        float4 v = make_float4(0.f, 0.f, 0.f, 0.f);
        if ((unsigned)gr < 192u && (unsigned)gc0 < 192u) {
            float4 w = *(const float4*)(inb + gr * 192 + gc0);
            v.x = (float)__float2uint_rz(w.x);
            v.y = (float)__float2uint_rz(w.y);
            v.z = (float)__float2uint_rz(w.z);
            v.w = (float)__float2uint_rz(w.w);
        }
        *(float4*)&Tsh[r * T_COLS + t4 * 4] = v;
    }

    // ---- Prologue B: per-chunk descriptors for this slice ----
    // Chunk u covers elements [4u,4u+4) of the 38416-elem 16-x region.
    // Element e: xi=e/2401, rr=e%2401 -> w=rr/49 (wy,wx), p=rr%49 (ty,tx);
    // smem offset = (wy+ty)*T_COLS + (xi+wx+tx) + 2 (column shift);
    // runtime adds 16*xg. Chunks past NCHUNKS are clamped (stores guarded).
    if (tid < SLICE) {
        int u = ubase + tid;
        if (u >= NCHUNKS) u = NCHUNKS - 1;
        unsigned short off[4];
#pragma unroll
        for (int j = 0; j < 4; j++) {
            int e  = 4 * u + j;
            int xi = e / 2401;
            int rr = e - xi * 2401;
            int w  = rr / 49;
            int p  = rr - w * 49;
            int wy = w / 7, wx = w - wy * 7;
            int ty = p / 7, tx = p - ty * 7;
            off[j] = (unsigned short)((wy + ty) * T_COLS + (xi + wx + tx) + 2);
        }
        Dsh[tid] = make_ushort4(off[0], off[1], off[2], off[3]);
    }
    __syncthreads();

    // ---- Main store stream: units of 3 coalesced STG.128 ----
    float4* rowout4 = (float4*)(out + (size_t)rowid * ROW_ELEMS);

#pragma unroll 1
    for (int idx = tid; idx < NUNITS; idx += NT) {
        int xgp = idx / SLICE;           // 0..3 (triple of x-groups)
        int uu  = idx - xgp * SLICE;     // 0..259, u-major: lanes coalesced
        int u   = ubase + uu;
        if (u < NCHUNKS) {               // warp-uniform except at slice edge
            ushort4 d = Dsh[uu];
            int xg0 = 3 * xgp;
            int st0 = xg0 * 16;

            // Base pointers per unit; inner loop uses immediate offsets j*16
            const float* p0 = Tsh + d.x + st0;
            const float* p1 = Tsh + d.y + st0;
            const float* p2 = Tsh + d.z + st0;
            const float* p3 = Tsh + d.w + st0;

            float4* gp = rowout4 + u + (size_t)xg0 * XG_STRIDE;

#pragma unroll
            for (int j = 0; j < 3; j++) {
                float4 v;
                v.x = p0[j * 16];
                v.y = p1[j * 16];
                v.z = p2[j * 16];
                v.w = p3[j * 16];
                __stcs(gp + (size_t)j * XG_STRIDE, v);
            }
        }
    }
}

// ---------------------------------------------------------------- launcher

extern "C" void kernel_launch(void* const* d_in, const int* in_sizes, int n_in,
                              void* d_out, int out_size) {
    const float* in = (const float*)d_in[0];
    // d_in[1] = search_range (fixed at 3: cv=7, offset=0 baked into descriptors)

    dim3 grid(37, 384);                  // x=slice fastest -> waves = 16 full rows
    main_k<<<grid, NT>>>(in, (float*)d_out);
}